// round 2
// baseline (speedup 1.0000x reference)
#include <cuda_runtime.h>

#define N_POINTS  131072
#define N_CENTERS 1024
#define DIM       128

#define BM 64
#define BN 64
#define BK 32
#define TM 4
#define TN 4
#define XPAD (BM + 4)
#define CPAD (BN + 4)

// Scratch (no cudaMalloc allowed) — __device__ globals.
__device__ float g_c2[N_CENTERS];
__device__ float g_x2[N_POINTS];

// One warp per row: sum of squares of a 128-float row. which==0 -> g_c2, which==1 -> g_x2.
__global__ void rownorm_kernel(const float* __restrict__ m, int rows, int which) {
    int warp = (blockIdx.x * blockDim.x + threadIdx.x) >> 5;
    int lane = threadIdx.x & 31;
    if (warp >= rows) return;
    const float4* r = reinterpret_cast<const float4*>(m + (size_t)warp * DIM);
    float4 v = r[lane];  // 32 lanes * 4 floats = 128
    float s = v.x * v.x + v.y * v.y + v.z * v.z + v.w * v.w;
    #pragma unroll
    for (int o = 16; o; o >>= 1) s += __shfl_xor_sync(0xffffffffu, s, o);
    if (lane == 0) {
        float* out = which ? g_x2 : g_c2;
        out[warp] = s;
    }
}

// Fused cdist^2 + min/argmin.
// Block: 256 threads (tx=tid&15, ty=tid>>4), tile BM=64 points x BN=64 centers,
// K chunked by BK=32. Each thread owns a 4x4 accumulator tile.
// score = c2[k] - 2*dot(x,c); cost = max(x2 + min_score, 0).
__global__ __launch_bounds__(256) void kmeans_kernel(
    const float* __restrict__ x,
    const float* __restrict__ c,
    float* __restrict__ out,
    int write_idx)
{
    __shared__ float Xs[BK][XPAD];
    __shared__ float Cs[BK][CPAD];
    __shared__ float redD[BM][17];
    __shared__ int   redI[BM][17];

    const int tid = threadIdx.x;
    const int tx = tid & 15;
    const int ty = tid >> 4;
    const int row0 = blockIdx.x * BM;

    float best[TM];
    int   bidx[TM];
    #pragma unroll
    for (int i = 0; i < TM; i++) { best[i] = 3.402823e38f; bidx[i] = 0; }

    for (int n0 = 0; n0 < N_CENTERS; n0 += BN) {
        float acc[TM][TN];
        #pragma unroll
        for (int i = 0; i < TM; i++)
            #pragma unroll
            for (int j = 0; j < TN; j++) acc[i][j] = 0.0f;

        for (int k0 = 0; k0 < DIM; k0 += BK) {
            // Load 64x32 tiles of x and centers (transposed into smem, K-major).
            // 512 float4 per tile, 256 threads -> 2 float4 each.
            #pragma unroll
            for (int it = 0; it < 2; it++) {
                int v  = tid + it * 256;
                int k4 = v & 7;        // which float4 along K
                int r  = v >> 3;       // row within tile (0..63)
                float4 xv = *reinterpret_cast<const float4*>(
                    x + (size_t)(row0 + r) * DIM + k0 + k4 * 4);
                Xs[k4 * 4 + 0][r] = xv.x;
                Xs[k4 * 4 + 1][r] = xv.y;
                Xs[k4 * 4 + 2][r] = xv.z;
                Xs[k4 * 4 + 3][r] = xv.w;
                float4 cv = *reinterpret_cast<const float4*>(
                    c + (size_t)(n0 + r) * DIM + k0 + k4 * 4);
                Cs[k4 * 4 + 0][r] = cv.x;
                Cs[k4 * 4 + 1][r] = cv.y;
                Cs[k4 * 4 + 2][r] = cv.z;
                Cs[k4 * 4 + 3][r] = cv.w;
            }
            __syncthreads();

            #pragma unroll
            for (int kk = 0; kk < BK; kk++) {
                float4 xv = *reinterpret_cast<const float4*>(&Xs[kk][ty * TM]);
                float4 cv = *reinterpret_cast<const float4*>(&Cs[kk][tx * TN]);
                float xa[TM] = {xv.x, xv.y, xv.z, xv.w};
                float ca[TN] = {cv.x, cv.y, cv.z, cv.w};
                #pragma unroll
                for (int i = 0; i < TM; i++)
                    #pragma unroll
                    for (int j = 0; j < TN; j++)
                        acc[i][j] = fmaf(xa[i], ca[j], acc[i][j]);
            }
            __syncthreads();
        }

        // Epilogue for this center tile: score = c2 - 2*dot, running min.
        // j ascending + strict < preserves first-occurrence argmin per thread.
        #pragma unroll
        for (int j = 0; j < TN; j++) {
            int cidx = n0 + tx * TN + j;
            float c2 = g_c2[cidx];
            #pragma unroll
            for (int i = 0; i < TM; i++) {
                float sc = fmaf(-2.0f, acc[i][j], c2);
                if (sc < best[i]) { best[i] = sc; bidx[i] = cidx; }
            }
        }
    }

    // Cross-thread (16 tx lanes per row) reduction.
    #pragma unroll
    for (int i = 0; i < TM; i++) {
        redD[ty * TM + i][tx] = best[i];
        redI[ty * TM + i][tx] = bidx[i];
    }
    __syncthreads();

    if (tid < BM) {
        float b = redD[tid][0];
        int  bi = redI[tid][0];
        #pragma unroll
        for (int t = 1; t < 16; t++) {
            float d = redD[tid][t];
            int  ii = redI[tid][t];
            if (d < b || (d == b && ii < bi)) { b = d; bi = ii; }
        }
        int row = row0 + tid;
        float cost = g_x2[row] + b;
        out[row] = cost > 0.0f ? cost : 0.0f;
        if (write_idx) out[N_POINTS + row] = (float)bi;
    }
}

extern "C" void kernel_launch(void* const* d_in, const int* in_sizes, int n_in,
                              void* d_out, int out_size) {
    const float* x = (const float*)d_in[0];       // [131072, 128]
    const float* c = (const float*)d_in[1];       // [1024, 128]
    float* out = (float*)d_out;

    // c2: 1024 rows, 8 warps/block -> 128 blocks
    rownorm_kernel<<<N_CENTERS / 8, 256>>>(c, N_CENTERS, 0);
    // x2: 131072 rows -> 16384 blocks
    rownorm_kernel<<<N_POINTS / 8, 256>>>(x, N_POINTS, 1);

    int write_idx = (out_size >= 2 * N_POINTS) ? 1 : 0;
    kmeans_kernel<<<N_POINTS / BM, 256>>>(x, c, out, write_idx);
}

// round 5
// speedup vs baseline: 1.8869x; 1.8869x over previous
#include <cuda_runtime.h>
#include <cuda_bf16.h>
#include <cstdint>

#define N_POINTS  131072
#define N_CENTERS 1024
#define DIM       128
#define BM        128
#define NC        128
#define NCHUNK    8

// ---- smem byte offsets (dynamic smem) ----
#define SM_XH   0
#define SM_XL   32768
#define SM_CB   65536            // + buf*65536 ; CL part = +32768
#define SM_C2   196608           // + buf*512
#define SM_RED  197632           // 128 rows * 2 wc * 16B
#define SMEM_TOTAL 201728

// swizzled byte offset inside a [128 rows x 256B] tile
#define SWZ(r, kb) ((uint32_t)((r) * 256 + ((kb) ^ (((r) & 7) << 4))))

// ---- device scratch (no cudaMalloc allowed) ----
__device__ __align__(16) __nv_bfloat16 g_ch[N_CENTERS * DIM];
__device__ __align__(16) __nv_bfloat16 g_cl[N_CENTERS * DIM];
__device__ float g_c2[N_CENTERS];

// =============================== PTX helpers (sm_80-era, target-agnostic) ===========
__device__ __forceinline__ uint32_t smem_u32(const void* p) {
    uint32_t a;
    asm("{ .reg .u64 t; cvta.to.shared.u64 t, %1; cvt.u32.u64 %0, t; }" : "=r"(a) : "l"(p));
    return a;
}
__device__ __forceinline__ void ldsm4(uint32_t& r0, uint32_t& r1, uint32_t& r2, uint32_t& r3,
                                      uint32_t addr) {
    asm volatile("ldmatrix.sync.aligned.m8n8.x4.shared.b16 {%0,%1,%2,%3}, [%4];"
                 : "=r"(r0), "=r"(r1), "=r"(r2), "=r"(r3) : "r"(addr));
}
__device__ __forceinline__ void mma16816(float* c, const uint32_t* a, uint32_t b0, uint32_t b1) {
    asm volatile("mma.sync.aligned.m16n8k16.row.col.f32.bf16.bf16.f32 "
                 "{%0,%1,%2,%3}, {%4,%5,%6,%7}, {%8,%9}, {%0,%1,%2,%3};"
                 : "+f"(c[0]), "+f"(c[1]), "+f"(c[2]), "+f"(c[3])
                 : "r"(a[0]), "r"(a[1]), "r"(a[2]), "r"(a[3]), "r"(b0), "r"(b1));
}
#define CP16(s, g) asm volatile("cp.async.cg.shared.global [%0], [%1], 16;" :: "r"(s), "l"(g))
#define CP4(s, g)  asm volatile("cp.async.ca.shared.global [%0], [%1], 4;"  :: "r"(s), "l"(g))
#define CPCOMMIT() asm volatile("cp.async.commit_group;" ::: "memory")
#define CPWAIT1()  asm volatile("cp.async.wait_group 1;" ::: "memory")

__device__ __forceinline__ uint32_t pack_bf16(float a, float b) {
    __nv_bfloat162 h = __floats2bfloat162_rn(a, b);
    return *reinterpret_cast<uint32_t*>(&h);
}
__device__ __forceinline__ void split2(float f, float& h, float& l) {
    __nv_bfloat16 hb = __float2bfloat16_rn(f);
    h = __bfloat162float(hb);
    l = f - h;
}
__device__ __forceinline__ bool better(float av, int ai, float bv, int bi) {
    return av < bv || (av == bv && ai < bi);
}
__device__ __forceinline__ void upd(float sc, int col, float& bv, int& bi, float& b2v, int& b2i) {
    if (sc < bv)        { b2v = bv; b2i = bi; bv = sc; bi = col; }
    else if (sc < b2v || (sc == b2v && col < b2i)) { b2v = sc; b2i = col; }
}
__device__ __forceinline__ void merge2(float& bv, int& bi, float& b2v, int& b2i,
                                       float ov, int oi, float o2v, int o2i) {
    if (better(ov, oi, bv, bi)) {
        float nv; int ni;
        if (better(bv, bi, o2v, o2i)) { nv = bv; ni = bi; } else { nv = o2v; ni = o2i; }
        bv = ov; bi = oi; b2v = nv; b2i = ni;
    } else if (better(ov, oi, b2v, b2i)) {
        b2v = ov; b2i = oi;
    }
}

// ======================= prologue: centers -> hi/lo bf16 + c2 =======================
__global__ void prep_centers(const float* __restrict__ c) {
    int warp = (blockIdx.x * blockDim.x + threadIdx.x) >> 5;
    int lane = threadIdx.x & 31;
    if (warp >= N_CENTERS) return;
    float4 v = reinterpret_cast<const float4*>(c + (size_t)warp * DIM)[lane];
    float s = v.x * v.x + v.y * v.y + v.z * v.z + v.w * v.w;
    float h0, l0, h1, l1, h2, l2, h3, l3;
    split2(v.x, h0, l0); split2(v.y, h1, l1); split2(v.z, h2, l2); split2(v.w, h3, l3);
    reinterpret_cast<uint2*>(g_ch + (size_t)warp * DIM)[lane] =
        make_uint2(pack_bf16(h0, h1), pack_bf16(h2, h3));
    reinterpret_cast<uint2*>(g_cl + (size_t)warp * DIM)[lane] =
        make_uint2(pack_bf16(l0, l1), pack_bf16(l2, l3));
    #pragma unroll
    for (int o = 16; o; o >>= 1) s += __shfl_xor_sync(0xffffffffu, s, o);
    if (lane == 0) g_c2[warp] = s;
}

// =============================== main kernel ===============================
__global__ __launch_bounds__(256, 1)
void kmeans_hmma_kernel(const float* __restrict__ x, const float* __restrict__ cen,
                        float* __restrict__ out, int write_idx) {
    extern __shared__ char smem[];
    const uint32_t sbase = smem_u32(smem);
    const int tid  = threadIdx.x;
    const int warp = tid >> 5;
    const int lane = tid & 31;
    const int wr = warp & 3;      // row group: rows wr*32 .. +32
    const int wc = warp >> 2;     // col group: cols wc*64 .. +64
    const int sub = lane >> 3;    // ldmatrix address group
    const int i8  = lane & 7;
    const int row0 = blockIdx.x * BM;

    // ---- stage x rows into XH/XL (hi/lo bf16, swizzled) ----
    {
        int r = tid >> 1, h = tid & 1;
        const float4* src = reinterpret_cast<const float4*>(
            x + (size_t)(row0 + r) * DIM + h * 64);
        #pragma unroll
        for (int j = 0; j < 8; j++) {
            float4 v0 = src[j * 2], v1 = src[j * 2 + 1];
            float h0,l0,h1,l1,h2,l2,h3,l3,h4,l4,h5,l5,h6,l6,h7,l7;
            split2(v0.x,h0,l0); split2(v0.y,h1,l1); split2(v0.z,h2,l2); split2(v0.w,h3,l3);
            split2(v1.x,h4,l4); split2(v1.y,h5,l5); split2(v1.z,h6,l6); split2(v1.w,h7,l7);
            uint32_t so = SWZ(r, h * 128 + j * 16);
            *reinterpret_cast<uint4*>(smem + SM_XH + so) =
                make_uint4(pack_bf16(h0,h1), pack_bf16(h2,h3), pack_bf16(h4,h5), pack_bf16(h6,h7));
            *reinterpret_cast<uint4*>(smem + SM_XL + so) =
                make_uint4(pack_bf16(l0,l1), pack_bf16(l2,l3), pack_bf16(l4,l5), pack_bf16(l6,l7));
        }
    }

    // ---- cp.async loader for a center chunk ----
    auto load_chunk = [&](int chunk, int buf) {
        const __nv_bfloat16* gh = g_ch + (size_t)chunk * NC * DIM;
        const __nv_bfloat16* gl = g_cl + (size_t)chunk * NC * DIM;
        uint32_t dh = sbase + SM_CB + buf * 65536;
        uint32_t dl = dh + 32768;
        #pragma unroll
        for (int it = 0; it < 8; it++) {
            int v = tid + it * 256;
            int r = v >> 4, c16 = v & 15;
            uint32_t so = SWZ(r, c16 * 16);
            CP16(dh + so, gh + r * DIM + c16 * 8);
            CP16(dl + so, gl + r * DIM + c16 * 8);
        }
        if (tid < NC)
            CP4(sbase + SM_C2 + buf * 512 + tid * 4, g_c2 + chunk * NC + tid);
    };

    load_chunk(0, 0);
    CPCOMMIT();
    __syncthreads();   // x tiles visible

    // per-thread ldmatrix address components
    const uint32_t aRowB = (uint32_t)(wr * 32 + ((sub & 1) << 3) + i8) * 256;
    const uint32_t aKb   = (uint32_t)((sub >> 1) << 4);
    const uint32_t bRowB = (uint32_t)(wc * 64 + ((sub >> 1) << 3) + i8) * 256;
    const uint32_t bKb   = (uint32_t)((sub & 1) << 4);
    const uint32_t kXor  = (uint32_t)(i8 << 4);

    // top-2 state: 4 rows per thread (mt*2 + half)
    float bv[4]  = {3.402823e38f, 3.402823e38f, 3.402823e38f, 3.402823e38f};
    float b2v[4] = {3.402823e38f, 3.402823e38f, 3.402823e38f, 3.402823e38f};
    int   bi[4]  = {0x7fffffff, 0x7fffffff, 0x7fffffff, 0x7fffffff};
    int   b2i[4] = {0x7fffffff, 0x7fffffff, 0x7fffffff, 0x7fffffff};

    #pragma unroll 1
    for (int ci = 0; ci < NCHUNK; ci++) {
        const int buf = ci & 1;
        if (ci + 1 < NCHUNK) load_chunk(ci + 1, (ci + 1) & 1);
        CPCOMMIT();
        CPWAIT1();
        __syncthreads();   // chunk ci visible to everyone

        float acc[2][8][4];
        #pragma unroll
        for (int mt = 0; mt < 2; mt++)
            #pragma unroll
            for (int nt = 0; nt < 8; nt++)
                #pragma unroll
                for (int q = 0; q < 4; q++) acc[mt][nt][q] = 0.f;

        const uint32_t cOff = SM_CB + buf * 65536;
        #pragma unroll 1
        for (int pass = 0; pass < 3; pass++) {
            const uint32_t aBase = sbase + (pass == 2 ? SM_XL : (uint32_t)SM_XH);
            const uint32_t bBase = sbase + cOff + (pass == 1 ? 32768u : 0u);
            #pragma unroll
            for (int ks = 0; ks < 8; ks++) {
                const uint32_t kb = ks * 32;
                uint32_t a[8];
                uint32_t aAddr = aBase + aRowB + ((kb + aKb) ^ kXor);
                ldsm4(a[0], a[1], a[2], a[3], aAddr);
                ldsm4(a[4], a[5], a[6], a[7], aAddr + 16 * 256);
                uint32_t b[16];
                #pragma unroll
                for (int p = 0; p < 4; p++) {
                    uint32_t bAddr = bBase + bRowB + p * 16 * 256 + ((kb + bKb) ^ kXor);
                    ldsm4(b[p*4], b[p*4+1], b[p*4+2], b[p*4+3], bAddr);
                }
                #pragma unroll
                for (int mt = 0; mt < 2; mt++)
                    #pragma unroll
                    for (int nt = 0; nt < 8; nt++)
                        mma16816(acc[mt][nt], &a[mt*4], b[(nt>>1)*4 + (nt&1)*2],
                                 b[(nt>>1)*4 + (nt&1)*2 + 1]);
            }
        }

        // epilogue: sc = c2 - 2*dot, running top-2
        const float* c2s = reinterpret_cast<const float*>(smem + SM_C2 + buf * 512);
        float2 c2r[8];
        #pragma unroll
        for (int nt = 0; nt < 8; nt++)
            c2r[nt] = *reinterpret_cast<const float2*>(&c2s[wc * 64 + nt * 8 + 2 * (lane & 3)]);
        const int colBase = ci * NC + wc * 64 + 2 * (lane & 3);
        #pragma unroll
        for (int nt = 0; nt < 8; nt++) {
            const int col = colBase + nt * 8;
            #pragma unroll
            for (int mt = 0; mt < 2; mt++) {
                upd(fmaf(-2.f, acc[mt][nt][0], c2r[nt].x), col,     bv[mt*2],   bi[mt*2],   b2v[mt*2],   b2i[mt*2]);
                upd(fmaf(-2.f, acc[mt][nt][1], c2r[nt].y), col + 1, bv[mt*2],   bi[mt*2],   b2v[mt*2],   b2i[mt*2]);
                upd(fmaf(-2.f, acc[mt][nt][2], c2r[nt].x), col,     bv[mt*2+1], bi[mt*2+1], b2v[mt*2+1], b2i[mt*2+1]);
                upd(fmaf(-2.f, acc[mt][nt][3], c2r[nt].y), col + 1, bv[mt*2+1], bi[mt*2+1], b2v[mt*2+1], b2i[mt*2+1]);
            }
        }
        __syncthreads();   // done reading this buffer before next prefetch overwrites it
    }

    // ---- quad butterfly: lanes sharing the same rows (t&3 varies) ----
    #pragma unroll
    for (int m = 1; m <= 2; m <<= 1) {
        #pragma unroll
        for (int rid = 0; rid < 4; rid++) {
            float ov  = __shfl_xor_sync(0xffffffffu, bv[rid],  m);
            int   oi  = __shfl_xor_sync(0xffffffffu, bi[rid],  m);
            float o2v = __shfl_xor_sync(0xffffffffu, b2v[rid], m);
            int   o2i = __shfl_xor_sync(0xffffffffu, b2i[rid], m);
            merge2(bv[rid], bi[rid], b2v[rid], b2i[rid], ov, oi, o2v, o2i);
        }
    }
    if ((lane & 3) == 0) {
        #pragma unroll
        for (int rid = 0; rid < 4; rid++) {
            int rl = wr * 32 + (rid >> 1) * 16 + (lane >> 2) + (rid & 1) * 8;
            *reinterpret_cast<float4*>(smem + SM_RED + (rl * 2 + wc) * 16) =
                make_float4(bv[rid], __int_as_float(bi[rid]), b2v[rid], __int_as_float(b2i[rid]));
        }
    }
    __syncthreads();

    // ---- final merge (2 col-warps) + exact fp32 top-2 refine ----
    if (tid < BM) {
        float4 e0 = *reinterpret_cast<float4*>(smem + SM_RED + (tid * 2 + 0) * 16);
        float4 e1 = *reinterpret_cast<float4*>(smem + SM_RED + (tid * 2 + 1) * 16);
        float fbv = e0.x; int fbi = __float_as_int(e0.y);
        float f2v = e0.z; int f2i = __float_as_int(e0.w);
        merge2(fbv, fbi, f2v, f2i, e1.x, __float_as_int(e1.y), e1.z, __float_as_int(e1.w));

        const int row = row0 + tid;
        const float4* xr = reinterpret_cast<const float4*>(x   + (size_t)row * DIM);
        const float4* c1 = reinterpret_cast<const float4*>(cen + (size_t)fbi * DIM);
        const float4* c2 = reinterpret_cast<const float4*>(cen + (size_t)f2i * DIM);
        float x2 = 0.f, d1 = 0.f, d2 = 0.f;
        #pragma unroll
        for (int k = 0; k < 32; k++) {
            float4 xv = xr[k], a = c1[k], b = c2[k];
            x2 = fmaf(xv.x, xv.x, x2); x2 = fmaf(xv.y, xv.y, x2);
            x2 = fmaf(xv.z, xv.z, x2); x2 = fmaf(xv.w, xv.w, x2);
            d1 = fmaf(xv.x, a.x, d1);  d1 = fmaf(xv.y, a.y, d1);
            d1 = fmaf(xv.z, a.z, d1);  d1 = fmaf(xv.w, a.w, d1);
            d2 = fmaf(xv.x, b.x, d2);  d2 = fmaf(xv.y, b.y, d2);
            d2 = fmaf(xv.z, b.z, d2);  d2 = fmaf(xv.w, b.w, d2);
        }
        float dist1 = fmaf(-2.f, d1, x2 + g_c2[fbi]);
        float dist2 = fmaf(-2.f, d2, x2 + g_c2[f2i]);
        float cost; int widx;
        if (better(dist2, f2i, dist1, fbi)) { cost = dist2; widx = f2i; }
        else                                 { cost = dist1; widx = fbi; }
        out[row] = cost > 0.f ? cost : 0.f;
        if (write_idx) out[N_POINTS + row] = (float)widx;
    }
}

// =============================== launch ===============================
extern "C" void kernel_launch(void* const* d_in, const int* in_sizes, int n_in,
                              void* d_out, int out_size) {
    const float* x = (const float*)d_in[0];   // [131072, 128]
    const float* c = (const float*)d_in[1];   // [1024, 128]
    float* out = (float*)d_out;

    prep_centers<<<N_CENTERS / 8, 256>>>(c);

    cudaFuncSetAttribute(kmeans_hmma_kernel,
                         cudaFuncAttributeMaxDynamicSharedMemorySize, SMEM_TOTAL);
    int write_idx = (out_size >= 2 * N_POINTS) ? 1 : 0;
    kmeans_hmma_kernel<<<N_POINTS / BM, 256, SMEM_TOTAL>>>(x, c, out, write_idx);
}

// round 8
// speedup vs baseline: 2.2125x; 1.1725x over previous
#include <cuda_runtime.h>
#include <cuda_bf16.h>
#include <cstdint>

#define N_POINTS  131072
#define N_CENTERS 1024
#define DIM       128
#define BM        128
#define NC        128
#define NCHUNK    8
#define NTHREADS  512

// ---- smem byte offsets (dynamic smem) ----
#define SM_XH   0
#define SM_XL   32768
#define SM_CB   65536            // CH at +0, CL at +32768 ; + buf*65536
#define SM_C2   196608           // + buf*512
#define SM_RED  197632           // 128 rows * 4 wc * 16B = 8192
#define SMEM_TOTAL 205824

// swizzled byte offset inside a [128 rows x 256B] tile
#define SWZ(r, kb) ((uint32_t)((r) * 256 + ((kb) ^ (((r) & 7) << 4))))

// ---- device scratch (no cudaMalloc allowed) ----
__device__ __align__(16) __nv_bfloat16 g_ch[N_CENTERS * DIM];
__device__ __align__(16) __nv_bfloat16 g_cl[N_CENTERS * DIM];
__device__ float g_c2[N_CENTERS];

// =============================== PTX helpers (target-agnostic sm_80 set) ===========
__device__ __forceinline__ uint32_t smem_u32(const void* p) {
    uint32_t a;
    asm("{ .reg .u64 t; cvta.to.shared.u64 t, %1; cvt.u32.u64 %0, t; }" : "=r"(a) : "l"(p));
    return a;
}
__device__ __forceinline__ void ldsm4(uint32_t& r0, uint32_t& r1, uint32_t& r2, uint32_t& r3,
                                      uint32_t addr) {
    asm volatile("ldmatrix.sync.aligned.m8n8.x4.shared.b16 {%0,%1,%2,%3}, [%4];"
                 : "=r"(r0), "=r"(r1), "=r"(r2), "=r"(r3) : "r"(addr));
}
__device__ __forceinline__ void mma16816(float* c, const uint32_t* a, uint32_t b0, uint32_t b1) {
    asm volatile("mma.sync.aligned.m16n8k16.row.col.f32.bf16.bf16.f32 "
                 "{%0,%1,%2,%3}, {%4,%5,%6,%7}, {%8,%9}, {%0,%1,%2,%3};"
                 : "+f"(c[0]), "+f"(c[1]), "+f"(c[2]), "+f"(c[3])
                 : "r"(a[0]), "r"(a[1]), "r"(a[2]), "r"(a[3]), "r"(b0), "r"(b1));
}
#define CP16(s, g) asm volatile("cp.async.cg.shared.global [%0], [%1], 16;" :: "r"(s), "l"(g))
#define CP4(s, g)  asm volatile("cp.async.ca.shared.global [%0], [%1], 4;"  :: "r"(s), "l"(g))
#define CPCOMMIT() asm volatile("cp.async.commit_group;" ::: "memory")
#define CPWAIT1()  asm volatile("cp.async.wait_group 1;" ::: "memory")

__device__ __forceinline__ uint32_t pack_bf16(float a, float b) {
    __nv_bfloat162 h = __floats2bfloat162_rn(a, b);
    return *reinterpret_cast<uint32_t*>(&h);
}
__device__ __forceinline__ void split2(float f, float& h, float& l) {
    __nv_bfloat16 hb = __float2bfloat16_rn(f);
    h = __bfloat162float(hb);
    l = f - h;
}
__device__ __forceinline__ bool better(float av, int ai, float bv, int bi) {
    return av < bv || (av == bv && ai < bi);
}
__device__ __forceinline__ void upd(float sc, int col, float& bv, int& bi, float& b2v, int& b2i) {
    if (sc < bv)        { b2v = bv; b2i = bi; bv = sc; bi = col; }
    else if (sc < b2v || (sc == b2v && col < b2i)) { b2v = sc; b2i = col; }
}
__device__ __forceinline__ void merge2(float& bv, int& bi, float& b2v, int& b2i,
                                       float ov, int oi, float o2v, int o2i) {
    if (better(ov, oi, bv, bi)) {
        float nv; int ni;
        if (better(bv, bi, o2v, o2i)) { nv = bv; ni = bi; } else { nv = o2v; ni = o2i; }
        bv = ov; bi = oi; b2v = nv; b2i = ni;
    } else if (better(ov, oi, b2v, b2i)) {
        b2v = ov; b2i = oi;
    }
}

// ======================= prologue: centers -> hi/lo bf16 + c2 =======================
__global__ void prep_centers(const float* __restrict__ c) {
    int warp = (blockIdx.x * blockDim.x + threadIdx.x) >> 5;
    int lane = threadIdx.x & 31;
    if (warp >= N_CENTERS) return;
    float4 v = reinterpret_cast<const float4*>(c + (size_t)warp * DIM)[lane];
    float s = v.x * v.x + v.y * v.y + v.z * v.z + v.w * v.w;
    float h0, l0, h1, l1, h2, l2, h3, l3;
    split2(v.x, h0, l0); split2(v.y, h1, l1); split2(v.z, h2, l2); split2(v.w, h3, l3);
    reinterpret_cast<uint2*>(g_ch + (size_t)warp * DIM)[lane] =
        make_uint2(pack_bf16(h0, h1), pack_bf16(h2, h3));
    reinterpret_cast<uint2*>(g_cl + (size_t)warp * DIM)[lane] =
        make_uint2(pack_bf16(l0, l1), pack_bf16(l2, l3));
    #pragma unroll
    for (int o = 16; o; o >>= 1) s += __shfl_xor_sync(0xffffffffu, s, o);
    if (lane == 0) g_c2[warp] = s;
}

// =============================== main kernel ===============================
__global__ __launch_bounds__(NTHREADS, 1)
void kmeans_hmma_kernel(const float* __restrict__ x, const float* __restrict__ cen,
                        float* __restrict__ out, int write_idx) {
    extern __shared__ char smem[];
    const uint32_t sbase = smem_u32(smem);
    const int tid  = threadIdx.x;
    const int warp = tid >> 5;
    const int lane = tid & 31;
    const int wr = warp & 3;      // row group: rows wr*32 .. +32
    const int wc = warp >> 2;     // col group: cols wc*32 .. +32
    const int sub = lane >> 3;
    const int i8  = lane & 7;
    const int row0 = blockIdx.x * BM;

    // ---- stage x rows into XH/XL (hi/lo bf16, swizzled). 512 threads: r=tid>>2 ----
    {
        int r = tid >> 2, h = tid & 3;   // thread covers elems [h*32, h*32+32)
        const float4* src = reinterpret_cast<const float4*>(
            x + (size_t)(row0 + r) * DIM + h * 32);
        #pragma unroll
        for (int j = 0; j < 4; j++) {
            float4 v0 = src[j * 2], v1 = src[j * 2 + 1];
            float h0,l0,h1,l1,h2,l2,h3,l3,h4,l4,h5,l5,h6,l6,h7,l7;
            split2(v0.x,h0,l0); split2(v0.y,h1,l1); split2(v0.z,h2,l2); split2(v0.w,h3,l3);
            split2(v1.x,h4,l4); split2(v1.y,h5,l5); split2(v1.z,h6,l6); split2(v1.w,h7,l7);
            uint32_t so = SWZ(r, h * 64 + j * 16);
            *reinterpret_cast<uint4*>(smem + SM_XH + so) =
                make_uint4(pack_bf16(h0,h1), pack_bf16(h2,h3), pack_bf16(h4,h5), pack_bf16(h6,h7));
            *reinterpret_cast<uint4*>(smem + SM_XL + so) =
                make_uint4(pack_bf16(l0,l1), pack_bf16(l2,l3), pack_bf16(l4,l5), pack_bf16(l6,l7));
        }
    }

    // ---- cp.async loader for a center chunk (CH + CL) ----
    auto load_chunk = [&](int chunk, int buf) {
        const __nv_bfloat16* gh = g_ch + (size_t)chunk * NC * DIM;
        const __nv_bfloat16* gl = g_cl + (size_t)chunk * NC * DIM;
        uint32_t dh = sbase + SM_CB + buf * 65536;
        uint32_t dl = dh + 32768;
        #pragma unroll
        for (int it = 0; it < 4; it++) {
            int v = tid + it * NTHREADS;
            int r = v >> 4, c16 = v & 15;
            uint32_t so = SWZ(r, c16 * 16);
            CP16(dh + so, gh + r * DIM + c16 * 8);
            CP16(dl + so, gl + r * DIM + c16 * 8);
        }
        if (tid < NC)
            CP4(sbase + SM_C2 + buf * 512 + tid * 4, g_c2 + chunk * NC + tid);
    };

    load_chunk(0, 0);
    CPCOMMIT();
    __syncthreads();   // x tiles visible

    // per-thread ldmatrix address components
    const uint32_t aRowB = (uint32_t)(wr * 32 + ((sub & 1) << 3) + i8) * 256;
    const uint32_t aKb   = (uint32_t)((sub >> 1) << 4);
    const uint32_t bRowB = (uint32_t)(wc * 32 + ((sub >> 1) << 3) + i8) * 256;
    const uint32_t bKb   = (uint32_t)((sub & 1) << 4);
    const uint32_t kXor  = (uint32_t)(i8 << 4);

    // top-2 state: 4 rows per thread
    float bv[4]  = {3.402823e38f, 3.402823e38f, 3.402823e38f, 3.402823e38f};
    float b2v[4] = {3.402823e38f, 3.402823e38f, 3.402823e38f, 3.402823e38f};
    int   bi[4]  = {0x7fffffff, 0x7fffffff, 0x7fffffff, 0x7fffffff};
    int   b2i[4] = {0x7fffffff, 0x7fffffff, 0x7fffffff, 0x7fffffff};

    #pragma unroll 1
    for (int ci = 0; ci < NCHUNK; ci++) {
        const int buf = ci & 1;
        if (ci + 1 < NCHUNK) load_chunk(ci + 1, (ci + 1) & 1);
        CPCOMMIT();
        CPWAIT1();
        __syncthreads();   // chunk ci visible

        float acc[2][4][4];
        #pragma unroll
        for (int mt = 0; mt < 2; mt++)
            #pragma unroll
            for (int nt = 0; nt < 4; nt++)
                #pragma unroll
                for (int q = 0; q < 4; q++) acc[mt][nt][q] = 0.f;

        const uint32_t chB = sbase + SM_CB + buf * 65536;
        const uint32_t clB = chB + 32768;
        #pragma unroll
        for (int ks = 0; ks < 8; ks++) {
            const uint32_t kb = ks * 32;
            const uint32_t aOff = aRowB + ((kb + aKb) ^ kXor);
            const uint32_t bOff = bRowB + ((kb + bKb) ^ kXor);
            uint32_t ah[8], al[8], bh[8], bl[8];
            ldsm4(ah[0], ah[1], ah[2], ah[3], sbase + SM_XH + aOff);
            ldsm4(ah[4], ah[5], ah[6], ah[7], sbase + SM_XH + aOff + 16 * 256);
            ldsm4(al[0], al[1], al[2], al[3], sbase + SM_XL + aOff);
            ldsm4(al[4], al[5], al[6], al[7], sbase + SM_XL + aOff + 16 * 256);
            ldsm4(bh[0], bh[1], bh[2], bh[3], chB + bOff);
            ldsm4(bh[4], bh[5], bh[6], bh[7], chB + bOff + 16 * 256);
            ldsm4(bl[0], bl[1], bl[2], bl[3], clB + bOff);
            ldsm4(bl[4], bl[5], bl[6], bl[7], clB + bOff + 16 * 256);
            #pragma unroll
            for (int mt = 0; mt < 2; mt++)
                #pragma unroll
                for (int nt = 0; nt < 4; nt++) {
                    const uint32_t* bp = (nt < 2) ? bh : bl;   // placeholder, replaced below
                }
            // pass 1: XH * CH ; pass 2: XH * CL ; pass 3: XL * CH
            #pragma unroll
            for (int mt = 0; mt < 2; mt++)
                #pragma unroll
                for (int nt = 0; nt < 4; nt++)
                    mma16816(acc[mt][nt], &ah[mt*4], bh[(nt>>1)*4 + (nt&1)*2],
                             bh[(nt>>1)*4 + (nt&1)*2 + 1]);
            #pragma unroll
            for (int mt = 0; mt < 2; mt++)
                #pragma unroll
                for (int nt = 0; nt < 4; nt++)
                    mma16816(acc[mt][nt], &ah[mt*4], bl[(nt>>1)*4 + (nt&1)*2],
                             bl[(nt>>1)*4 + (nt&1)*2 + 1]);
            #pragma unroll
            for (int mt = 0; mt < 2; mt++)
                #pragma unroll
                for (int nt = 0; nt < 4; nt++)
                    mma16816(acc[mt][nt], &al[mt*4], bh[(nt>>1)*4 + (nt&1)*2],
                             bh[(nt>>1)*4 + (nt&1)*2 + 1]);
        }

        // epilogue: sc = c2 - 2*dot, running top-2
        const float* c2s = reinterpret_cast<const float*>(smem + SM_C2 + buf * 512);
        float2 c2r[4];
        #pragma unroll
        for (int nt = 0; nt < 4; nt++)
            c2r[nt] = *reinterpret_cast<const float2*>(&c2s[wc * 32 + nt * 8 + 2 * (lane & 3)]);
        const int colBase = ci * NC + wc * 32 + 2 * (lane & 3);
        #pragma unroll
        for (int nt = 0; nt < 4; nt++) {
            const int col = colBase + nt * 8;
            #pragma unroll
            for (int mt = 0; mt < 2; mt++) {
                upd(fmaf(-2.f, acc[mt][nt][0], c2r[nt].x), col,     bv[mt*2],   bi[mt*2],   b2v[mt*2],   b2i[mt*2]);
                upd(fmaf(-2.f, acc[mt][nt][1], c2r[nt].y), col + 1, bv[mt*2],   bi[mt*2],   b2v[mt*2],   b2i[mt*2]);
                upd(fmaf(-2.f, acc[mt][nt][2], c2r[nt].x), col,     bv[mt*2+1], bi[mt*2+1], b2v[mt*2+1], b2i[mt*2+1]);
                upd(fmaf(-2.f, acc[mt][nt][3], c2r[nt].y), col + 1, bv[mt*2+1], bi[mt*2+1], b2v[mt*2+1], b2i[mt*2+1]);
            }
        }
        __syncthreads();   // done reading buffer before next prefetch overwrites it
    }

    // ---- quad butterfly (lanes sharing the same rows) ----
    #pragma unroll
    for (int m = 1; m <= 2; m <<= 1) {
        #pragma unroll
        for (int rid = 0; rid < 4; rid++) {
            float ov  = __shfl_xor_sync(0xffffffffu, bv[rid],  m);
            int   oi  = __shfl_xor_sync(0xffffffffu, bi[rid],  m);
            float o2v = __shfl_xor_sync(0xffffffffu, b2v[rid], m);
            int   o2i = __shfl_xor_sync(0xffffffffu, b2i[rid], m);
            merge2(bv[rid], bi[rid], b2v[rid], b2i[rid], ov, oi, o2v, o2i);
        }
    }
    if ((lane & 3) == 0) {
        #pragma unroll
        for (int rid = 0; rid < 4; rid++) {
            int rl = wr * 32 + (rid >> 1) * 16 + (lane >> 2) + (rid & 1) * 8;
            *reinterpret_cast<float4*>(smem + SM_RED + (rl * 4 + wc) * 16) =
                make_float4(bv[rid], __int_as_float(bi[rid]), b2v[rid], __int_as_float(b2i[rid]));
        }
    }
    __syncthreads();

    // ---- final merge (4 col-warps) + exact fp32 top-2 refine ----
    if (tid < BM) {
        float4 e0 = *reinterpret_cast<float4*>(smem + SM_RED + (tid * 4 + 0) * 16);
        float fbv = e0.x; int fbi = __float_as_int(e0.y);
        float f2v = e0.z; int f2i = __float_as_int(e0.w);
        #pragma unroll
        for (int wcc = 1; wcc < 4; wcc++) {
            float4 e = *reinterpret_cast<float4*>(smem + SM_RED + (tid * 4 + wcc) * 16);
            merge2(fbv, fbi, f2v, f2i, e.x, __float_as_int(e.y), e.z, __float_as_int(e.w));
        }

        const int row = row0 + tid;
        const float4* xr = reinterpret_cast<const float4*>(x   + (size_t)row * DIM);
        const float4* c1 = reinterpret_cast<const float4*>(cen + (size_t)fbi * DIM);
        const float4* c2 = reinterpret_cast<const float4*>(cen + (size_t)f2i * DIM);
        float x2 = 0.f, d1 = 0.f, d2 = 0.f;
        #pragma unroll
        for (int k = 0; k < 32; k++) {
            float4 xv = xr[k], a = c1[k], b = c2[k];
            x2 = fmaf(xv.x, xv.x, x2); x2 = fmaf(xv.y, xv.y, x2);
            x2 = fmaf(xv.z, xv.z, x2); x2 = fmaf(xv.w, xv.w, x2);
            d1 = fmaf(xv.x, a.x, d1);  d1 = fmaf(xv.y, a.y, d1);
            d1 = fmaf(xv.z, a.z, d1);  d1 = fmaf(xv.w, a.w, d1);
            d2 = fmaf(xv.x, b.x, d2);  d2 = fmaf(xv.y, b.y, d2);
            d2 = fmaf(xv.z, b.z, d2);  d2 = fmaf(xv.w, b.w, d2);
        }
        float dist1 = fmaf(-2.f, d1, x2 + g_c2[fbi]);
        float dist2 = fmaf(-2.f, d2, x2 + g_c2[f2i]);
        float cost; int widx;
        if (better(dist2, f2i, dist1, fbi)) { cost = dist2; widx = f2i; }
        else                                 { cost = dist1; widx = fbi; }
        out[row] = cost > 0.f ? cost : 0.f;
        if (write_idx) out[N_POINTS + row] = (float)widx;
    }
}

// =============================== launch ===============================
extern "C" void kernel_launch(void* const* d_in, const int* in_sizes, int n_in,
                              void* d_out, int out_size) {
    const float* x = (const float*)d_in[0];   // [131072, 128]
    const float* c = (const float*)d_in[1];   // [1024, 128]
    float* out = (float*)d_out;

    prep_centers<<<N_CENTERS / 8, 256>>>(c);

    cudaFuncSetAttribute(kmeans_hmma_kernel,
                         cudaFuncAttributeMaxDynamicSharedMemorySize, SMEM_TOTAL);
    int write_idx = (out_size >= 2 * N_POINTS) ? 1 : 0;
    kmeans_hmma_kernel<<<N_POINTS / BM, NTHREADS, SMEM_TOTAL>>>(x, c, out, write_idx);
}

// round 9
// speedup vs baseline: 2.5813x; 1.1667x over previous
#include <cuda_runtime.h>
#include <cuda_bf16.h>
#include <cstdint>

#define N_POINTS  131072
#define N_CENTERS 1024
#define DIM       128
#define BM        64
#define NC        64
#define NCHUNK    16
#define NTHREADS  256

// ---- smem byte offsets (dynamic smem) ----
#define SM_XH   0                 // 64 rows * 256B = 16384
#define SM_XL   16384
#define SM_CB   32768             // CH(16K)+CL(16K) per buf ; + buf*32768
#define SM_C2   98304             // + buf*256
#define SM_RED  98816             // 64 rows * 4 wc * 16B = 4096
#define SMEM_TOTAL 102912

// swizzled byte offset inside a [rows x 256B] tile
#define SWZ(r, kb) ((uint32_t)((r) * 256 + ((kb) ^ (((r) & 7) << 4))))

// ---- device scratch (no cudaMalloc allowed) ----
__device__ __align__(16) __nv_bfloat16 g_ch[N_CENTERS * DIM];
__device__ __align__(16) __nv_bfloat16 g_cl[N_CENTERS * DIM];
__device__ float g_c2[N_CENTERS];

// =============================== PTX helpers (target-agnostic sm_80 set) ===========
__device__ __forceinline__ uint32_t smem_u32(const void* p) {
    uint32_t a;
    asm("{ .reg .u64 t; cvta.to.shared.u64 t, %1; cvt.u32.u64 %0, t; }" : "=r"(a) : "l"(p));
    return a;
}
__device__ __forceinline__ void ldsm4(uint32_t& r0, uint32_t& r1, uint32_t& r2, uint32_t& r3,
                                      uint32_t addr) {
    asm volatile("ldmatrix.sync.aligned.m8n8.x4.shared.b16 {%0,%1,%2,%3}, [%4];"
                 : "=r"(r0), "=r"(r1), "=r"(r2), "=r"(r3) : "r"(addr));
}
__device__ __forceinline__ void mma16816(float* c, const uint32_t* a, uint32_t b0, uint32_t b1) {
    asm volatile("mma.sync.aligned.m16n8k16.row.col.f32.bf16.bf16.f32 "
                 "{%0,%1,%2,%3}, {%4,%5,%6,%7}, {%8,%9}, {%0,%1,%2,%3};"
                 : "+f"(c[0]), "+f"(c[1]), "+f"(c[2]), "+f"(c[3])
                 : "r"(a[0]), "r"(a[1]), "r"(a[2]), "r"(a[3]), "r"(b0), "r"(b1));
}
#define CP16(s, g) asm volatile("cp.async.cg.shared.global [%0], [%1], 16;" :: "r"(s), "l"(g))
#define CP4(s, g)  asm volatile("cp.async.ca.shared.global [%0], [%1], 4;"  :: "r"(s), "l"(g))
#define CPCOMMIT() asm volatile("cp.async.commit_group;" ::: "memory")
#define CPWAIT1()  asm volatile("cp.async.wait_group 1;" ::: "memory")

__device__ __forceinline__ uint32_t pack_bf16(float a, float b) {
    __nv_bfloat162 h = __floats2bfloat162_rn(a, b);
    return *reinterpret_cast<uint32_t*>(&h);
}
__device__ __forceinline__ void split2(float f, float& h, float& l) {
    __nv_bfloat16 hb = __float2bfloat16_rn(f);
    h = __bfloat162float(hb);
    l = f - h;
}
__device__ __forceinline__ bool better(float av, int ai, float bv, int bi) {
    return av < bv || (av == bv && ai < bi);
}
__device__ __forceinline__ void upd(float sc, int col, float& bv, int& bi, float& b2v, int& b2i) {
    if (sc < bv)        { b2v = bv; b2i = bi; bv = sc; bi = col; }
    else if (sc < b2v || (sc == b2v && col < b2i)) { b2v = sc; b2i = col; }
}
__device__ __forceinline__ void merge2(float& bv, int& bi, float& b2v, int& b2i,
                                       float ov, int oi, float o2v, int o2i) {
    if (better(ov, oi, bv, bi)) {
        float nv; int ni;
        if (better(bv, bi, o2v, o2i)) { nv = bv; ni = bi; } else { nv = o2v; ni = o2i; }
        bv = ov; bi = oi; b2v = nv; b2i = ni;
    } else if (better(ov, oi, b2v, b2i)) {
        b2v = ov; b2i = oi;
    }
}

// ======================= prologue: centers -> hi/lo bf16 + c2 =======================
__global__ void prep_centers(const float* __restrict__ c) {
    int warp = (blockIdx.x * blockDim.x + threadIdx.x) >> 5;
    int lane = threadIdx.x & 31;
    if (warp >= N_CENTERS) return;
    float4 v = reinterpret_cast<const float4*>(c + (size_t)warp * DIM)[lane];
    float s = v.x * v.x + v.y * v.y + v.z * v.z + v.w * v.w;
    float h0, l0, h1, l1, h2, l2, h3, l3;
    split2(v.x, h0, l0); split2(v.y, h1, l1); split2(v.z, h2, l2); split2(v.w, h3, l3);
    reinterpret_cast<uint2*>(g_ch + (size_t)warp * DIM)[lane] =
        make_uint2(pack_bf16(h0, h1), pack_bf16(h2, h3));
    reinterpret_cast<uint2*>(g_cl + (size_t)warp * DIM)[lane] =
        make_uint2(pack_bf16(l0, l1), pack_bf16(l2, l3));
    #pragma unroll
    for (int o = 16; o; o >>= 1) s += __shfl_xor_sync(0xffffffffu, s, o);
    if (lane == 0) g_c2[warp] = s;
}

// =============================== main kernel ===============================
__global__ __launch_bounds__(NTHREADS, 2)
void kmeans_hmma_kernel(const float* __restrict__ x, const float* __restrict__ cen,
                        float* __restrict__ out, int write_idx) {
    extern __shared__ char smem[];
    const uint32_t sbase = smem_u32(smem);
    const int tid  = threadIdx.x;
    const int warp = tid >> 5;
    const int lane = tid & 31;
    const int wr = warp & 1;      // row group: rows wr*32 .. +32
    const int wc = warp >> 1;     // col group: cols wc*16 .. +16
    const int sub = lane >> 3;
    const int i8  = lane & 7;
    const int row0 = blockIdx.x * BM;

    // ---- stage x rows into XH/XL (hi/lo bf16, swizzled). 256 threads: r=tid>>2 ----
    {
        int r = tid >> 2, h = tid & 3;   // thread covers elems [h*32, h*32+32)
        const float4* src = reinterpret_cast<const float4*>(
            x + (size_t)(row0 + r) * DIM + h * 32);
        #pragma unroll
        for (int j = 0; j < 4; j++) {
            float4 v0 = src[j * 2], v1 = src[j * 2 + 1];
            float h0,l0,h1,l1,h2,l2,h3,l3,h4,l4,h5,l5,h6,l6,h7,l7;
            split2(v0.x,h0,l0); split2(v0.y,h1,l1); split2(v0.z,h2,l2); split2(v0.w,h3,l3);
            split2(v1.x,h4,l4); split2(v1.y,h5,l5); split2(v1.z,h6,l6); split2(v1.w,h7,l7);
            uint32_t so = SWZ(r, h * 64 + j * 16);
            *reinterpret_cast<uint4*>(smem + SM_XH + so) =
                make_uint4(pack_bf16(h0,h1), pack_bf16(h2,h3), pack_bf16(h4,h5), pack_bf16(h6,h7));
            *reinterpret_cast<uint4*>(smem + SM_XL + so) =
                make_uint4(pack_bf16(l0,l1), pack_bf16(l2,l3), pack_bf16(l4,l5), pack_bf16(l6,l7));
        }
    }

    // ---- cp.async loader for a center chunk (CH + CL, 64 centers) ----
    auto load_chunk = [&](int chunk, int buf) {
        const __nv_bfloat16* gh = g_ch + (size_t)chunk * NC * DIM;
        const __nv_bfloat16* gl = g_cl + (size_t)chunk * NC * DIM;
        uint32_t dh = sbase + SM_CB + buf * 32768;
        uint32_t dl = dh + 16384;
        #pragma unroll
        for (int it = 0; it < 4; it++) {
            int v = tid + it * NTHREADS;
            int r = v >> 4, c16 = v & 15;
            uint32_t so = SWZ(r, c16 * 16);
            CP16(dh + so, gh + r * DIM + c16 * 8);
            CP16(dl + so, gl + r * DIM + c16 * 8);
        }
        if (tid < NC)
            CP4(sbase + SM_C2 + buf * 256 + tid * 4, g_c2 + chunk * NC + tid);
    };

    load_chunk(0, 0);
    CPCOMMIT();
    __syncthreads();   // x tiles visible

    // per-thread ldmatrix address components
    const uint32_t aRowB = (uint32_t)(wr * 32 + ((sub & 1) << 3) + i8) * 256;
    const uint32_t aKb   = (uint32_t)((sub >> 1) << 4);
    const uint32_t bRowB = (uint32_t)(wc * 16 + ((sub >> 1) << 3) + i8) * 256;
    const uint32_t bKb   = (uint32_t)((sub & 1) << 4);
    const uint32_t kXor  = (uint32_t)(i8 << 4);

    // top-2 state: 4 rows per thread
    float bv[4]  = {3.402823e38f, 3.402823e38f, 3.402823e38f, 3.402823e38f};
    float b2v[4] = {3.402823e38f, 3.402823e38f, 3.402823e38f, 3.402823e38f};
    int   bi[4]  = {0x7fffffff, 0x7fffffff, 0x7fffffff, 0x7fffffff};
    int   b2i[4] = {0x7fffffff, 0x7fffffff, 0x7fffffff, 0x7fffffff};

    #pragma unroll 1
    for (int ci = 0; ci < NCHUNK; ci++) {
        const int buf = ci & 1;
        if (ci + 1 < NCHUNK) load_chunk(ci + 1, (ci + 1) & 1);
        CPCOMMIT();
        CPWAIT1();
        __syncthreads();   // chunk ci visible

        float acc[2][2][4];
        #pragma unroll
        for (int mt = 0; mt < 2; mt++)
            #pragma unroll
            for (int nt = 0; nt < 2; nt++)
                #pragma unroll
                for (int q = 0; q < 4; q++) acc[mt][nt][q] = 0.f;

        const uint32_t chB = sbase + SM_CB + buf * 32768;
        const uint32_t clB = chB + 16384;
        #pragma unroll
        for (int ks = 0; ks < 8; ks++) {
            const uint32_t kb = ks * 32;
            const uint32_t aOff = aRowB + ((kb + aKb) ^ kXor);
            const uint32_t bOff = bRowB + ((kb + bKb) ^ kXor);
            uint32_t ah[8], al[8], bh[4], bl[4];
            ldsm4(ah[0], ah[1], ah[2], ah[3], sbase + SM_XH + aOff);
            ldsm4(ah[4], ah[5], ah[6], ah[7], sbase + SM_XH + aOff + 16 * 256);
            ldsm4(al[0], al[1], al[2], al[3], sbase + SM_XL + aOff);
            ldsm4(al[4], al[5], al[6], al[7], sbase + SM_XL + aOff + 16 * 256);
            ldsm4(bh[0], bh[1], bh[2], bh[3], chB + bOff);
            ldsm4(bl[0], bl[1], bl[2], bl[3], clB + bOff);
            // pass 1: XH * CH ; pass 2: XH * CL ; pass 3: XL * CH
            #pragma unroll
            for (int mt = 0; mt < 2; mt++)
                #pragma unroll
                for (int nt = 0; nt < 2; nt++)
                    mma16816(acc[mt][nt], &ah[mt*4], bh[nt*2], bh[nt*2 + 1]);
            #pragma unroll
            for (int mt = 0; mt < 2; mt++)
                #pragma unroll
                for (int nt = 0; nt < 2; nt++)
                    mma16816(acc[mt][nt], &ah[mt*4], bl[nt*2], bl[nt*2 + 1]);
            #pragma unroll
            for (int mt = 0; mt < 2; mt++)
                #pragma unroll
                for (int nt = 0; nt < 2; nt++)
                    mma16816(acc[mt][nt], &al[mt*4], bh[nt*2], bh[nt*2 + 1]);
        }

        // epilogue: sc = c2 - 2*dot, running top-2
        const float* c2s = reinterpret_cast<const float*>(smem + SM_C2 + buf * 256);
        float2 c2r[2];
        #pragma unroll
        for (int nt = 0; nt < 2; nt++)
            c2r[nt] = *reinterpret_cast<const float2*>(&c2s[wc * 16 + nt * 8 + 2 * (lane & 3)]);
        const int colBase = ci * NC + wc * 16 + 2 * (lane & 3);
        #pragma unroll
        for (int nt = 0; nt < 2; nt++) {
            const int col = colBase + nt * 8;
            #pragma unroll
            for (int mt = 0; mt < 2; mt++) {
                upd(fmaf(-2.f, acc[mt][nt][0], c2r[nt].x), col,     bv[mt*2],   bi[mt*2],   b2v[mt*2],   b2i[mt*2]);
                upd(fmaf(-2.f, acc[mt][nt][1], c2r[nt].y), col + 1, bv[mt*2],   bi[mt*2],   b2v[mt*2],   b2i[mt*2]);
                upd(fmaf(-2.f, acc[mt][nt][2], c2r[nt].x), col,     bv[mt*2+1], bi[mt*2+1], b2v[mt*2+1], b2i[mt*2+1]);
                upd(fmaf(-2.f, acc[mt][nt][3], c2r[nt].y), col + 1, bv[mt*2+1], bi[mt*2+1], b2v[mt*2+1], b2i[mt*2+1]);
            }
        }
        __syncthreads();   // done reading buffer before next prefetch overwrites it
    }

    // ---- quad butterfly (lanes sharing the same rows) ----
    #pragma unroll
    for (int m = 1; m <= 2; m <<= 1) {
        #pragma unroll
        for (int rid = 0; rid < 4; rid++) {
            float ov  = __shfl_xor_sync(0xffffffffu, bv[rid],  m);
            int   oi  = __shfl_xor_sync(0xffffffffu, bi[rid],  m);
            float o2v = __shfl_xor_sync(0xffffffffu, b2v[rid], m);
            int   o2i = __shfl_xor_sync(0xffffffffu, b2i[rid], m);
            merge2(bv[rid], bi[rid], b2v[rid], b2i[rid], ov, oi, o2v, o2i);
        }
    }
    if ((lane & 3) == 0) {
        #pragma unroll
        for (int rid = 0; rid < 4; rid++) {
            int rl = wr * 32 + (rid >> 1) * 16 + (lane >> 2) + (rid & 1) * 8;
            *reinterpret_cast<float4*>(smem + SM_RED + (rl * 4 + wc) * 16) =
                make_float4(bv[rid], __int_as_float(bi[rid]), b2v[rid], __int_as_float(b2i[rid]));
        }
    }
    __syncthreads();

    // ---- final merge (4 col-warps) + exact fp32 top-2 refine ----
    if (tid < BM) {
        float4 e0 = *reinterpret_cast<float4*>(smem + SM_RED + (tid * 4 + 0) * 16);
        float fbv = e0.x; int fbi = __float_as_int(e0.y);
        float f2v = e0.z; int f2i = __float_as_int(e0.w);
        #pragma unroll
        for (int wcc = 1; wcc < 4; wcc++) {
            float4 e = *reinterpret_cast<float4*>(smem + SM_RED + (tid * 4 + wcc) * 16);
            merge2(fbv, fbi, f2v, f2i, e.x, __float_as_int(e.y), e.z, __float_as_int(e.w));
        }

        const int row = row0 + tid;
        const float4* xr = reinterpret_cast<const float4*>(x   + (size_t)row * DIM);
        const float4* c1 = reinterpret_cast<const float4*>(cen + (size_t)fbi * DIM);
        const float4* c2 = reinterpret_cast<const float4*>(cen + (size_t)f2i * DIM);
        float x2 = 0.f, d1 = 0.f, d2 = 0.f;
        #pragma unroll
        for (int k = 0; k < 32; k++) {
            float4 xv = xr[k], a = c1[k], b = c2[k];
            x2 = fmaf(xv.x, xv.x, x2); x2 = fmaf(xv.y, xv.y, x2);
            x2 = fmaf(xv.z, xv.z, x2); x2 = fmaf(xv.w, xv.w, x2);
            d1 = fmaf(xv.x, a.x, d1);  d1 = fmaf(xv.y, a.y, d1);
            d1 = fmaf(xv.z, a.z, d1);  d1 = fmaf(xv.w, a.w, d1);
            d2 = fmaf(xv.x, b.x, d2);  d2 = fmaf(xv.y, b.y, d2);
            d2 = fmaf(xv.z, b.z, d2);  d2 = fmaf(xv.w, b.w, d2);
        }
        float dist1 = fmaf(-2.f, d1, x2 + g_c2[fbi]);
        float dist2 = fmaf(-2.f, d2, x2 + g_c2[f2i]);
        float cost; int widx;
        if (better(dist2, f2i, dist1, fbi)) { cost = dist2; widx = f2i; }
        else                                 { cost = dist1; widx = fbi; }
        out[row] = cost > 0.f ? cost : 0.f;
        if (write_idx) out[N_POINTS + row] = (float)widx;
    }
}

// =============================== launch ===============================
extern "C" void kernel_launch(void* const* d_in, const int* in_sizes, int n_in,
                              void* d_out, int out_size) {
    const float* x = (const float*)d_in[0];   // [131072, 128]
    const float* c = (const float*)d_in[1];   // [1024, 128]
    float* out = (float*)d_out;

    prep_centers<<<N_CENTERS / 8, 256>>>(c);

    cudaFuncSetAttribute(kmeans_hmma_kernel,
                         cudaFuncAttributeMaxDynamicSharedMemorySize, SMEM_TOTAL);
    int write_idx = (out_size >= 2 * N_POINTS) ? 1 : 0;
    kmeans_hmma_kernel<<<N_POINTS / BM, NTHREADS, SMEM_TOTAL>>>(x, c, out, write_idx);
}